// round 15
// baseline (speedup 1.0000x reference)
#include <cuda_runtime.h>
#include <cuda_bf16.h>

#define DD     16
#define NHEAD  8
#define LAYERS 8
#define FFD    16
#define KW     35
#define SEQIN  3500
#define NP     100
#define SS     101
#define HSTR   20      // s_h row stride (16B-aligned rows)
#define NT     128
#define QB     7       // query rows per attention task
#define NBLK   15      // ceil(SS/QB) -> 8*15 = 120 tasks
#define TSTR   104     // per-head slot stride in s_att regions (even)

// s_att float regions (each 8 heads * TSTR floats = 832)
#define QX_OFF 0
#define QY_OFF 832
#define KX_OFF 1664
#define KY_OFF 2496
#define VX_OFF 3328
#define VY_OFF 4160
#define ATT_SZ 4992    // also holds x (3500) during conv

typedef unsigned long long u64;

__device__ __forceinline__ float ex2f_fast(float x) {
    float y;
    asm("ex2.approx.ftz.f32 %0, %1;" : "=f"(y) : "f"(x));
    return y;
}
__device__ __forceinline__ float rcpf_fast(float x) {
    float y;
    asm("rcp.approx.ftz.f32 %0, %1;" : "=f"(y) : "f"(x));
    return y;
}
__device__ __forceinline__ u64 pk2(float lo, float hi) {
    u64 r; asm("mov.b64 %0, {%1, %2};" : "=l"(r) : "f"(lo), "f"(hi)); return r;
}
__device__ __forceinline__ void upk2(u64 v, float& lo, float& hi) {
    asm("mov.b64 {%0, %1}, %2;" : "=f"(lo), "=f"(hi) : "l"(v));
}
__device__ __forceinline__ u64 fma2_(u64 a, u64 b, u64 c) {
    u64 r; asm("fma.rn.f32x2 %0, %1, %2, %3;" : "=l"(r) : "l"(a), "l"(b), "l"(c)); return r;
}
__device__ __forceinline__ u64 mul2_(u64 a, u64 b) {
    u64 r; asm("mul.rn.f32x2 %0, %1, %2;" : "=l"(r) : "l"(a), "l"(b)); return r;
}
__device__ __forceinline__ u64 add2_(u64 a, u64 b) {
    u64 r; asm("add.rn.f32x2 %0, %1, %2;" : "=l"(r) : "l"(a), "l"(b)); return r;
}
__device__ __forceinline__ u64 exp2m(u64 sc2) {
    float a, b; upk2(sc2, a, b);
    return pk2(ex2f_fast(a), ex2f_fast(b));
}

// FMA-pipe packed exp2: z-trick rint + deg-4 Taylor + exponent insert via
// (z_bits<<23) == n<<23 (low 9 bits of 0x4B400000 are zero). All constants
// passed in (hoisted to loop-invariant registers by the caller).
__device__ __forceinline__ u64 exp2poly(u64 sc2, u64 C12, u64 mC12, u64 mONE,
                                        u64 c4, u64 c3, u64 c2, u64 c1, u64 ONE) {
    u64 z2  = add2_(sc2, C12);           // n in low mantissa bits
    u64 nf2 = add2_(z2, mC12);           // n as float (exact)
    u64 f2  = fma2_(nf2, mONE, sc2);     // f = sc - n, f in [-0.5, 0.5]
    u64 p = fma2_(f2, c4, c3);
    p = fma2_(f2, p, c2);
    p = fma2_(f2, p, c1);
    p = fma2_(f2, p, ONE);
    float zl, zh, pl, ph;
    upk2(z2, zl, zh);
    upk2(p,  pl, ph);
    float el = __int_as_float(__float_as_int(pl) + (__float_as_int(zl) << 23));
    float eh = __int_as_float(__float_as_int(ph) + (__float_as_int(zh) << 23));
    return pk2(el, eh);
}

// packed 16-dot: a2 = 8 packed activation pairs (regs), w2 = smem weight row as u64*
__device__ __forceinline__ float dot16p(const u64* a2, const u64* __restrict__ w2, float bias) {
    u64 acc = pk2(bias, 0.f);
    #pragma unroll
    for (int j = 0; j < 8; j++) acc = fma2_(a2[j], w2[j], acc);
    float lo, hi; upk2(acc, lo, hi);
    return lo + hi;
}

__global__ __launch_bounds__(NT, 5) void TorrinE0_fused_kernel(
    const float* __restrict__ x,      const float* __restrict__ conv_w, const float* __restrict__ conv_b,
    const float* __restrict__ cls_emb,const float* __restrict__ Wqkv,   const float* __restrict__ bqkv,
    const float* __restrict__ Wo,     const float* __restrict__ bo,
    const float* __restrict__ W1,     const float* __restrict__ b1,
    const float* __restrict__ W2,     const float* __restrict__ b2,
    const float* __restrict__ ln1_g,  const float* __restrict__ ln1_b,
    const float* __restrict__ ln2_g,  const float* __restrict__ ln2_b,
    const float* __restrict__ lnf_g,  const float* __restrict__ lnf_b,
    const float* __restrict__ end_w,  const float* __restrict__ end_b,
    const float* __restrict__ head_w, const float* __restrict__ head_b,
    float* __restrict__ out)
{
    __shared__ __align__(16) float s_h   [SS * HSTR];
    __shared__ __align__(16) float s_att [ATT_SZ];
    __shared__ __align__(16) float s_Wqkv[768];       // holds conv_w (560) during conv
    __shared__ __align__(16) float s_bqkv[48];
    __shared__ __align__(16) float s_Wo[256], s_W1[256], s_W2[256];
    __shared__ float s_bo[16],  s_b1[16], s_b2[16];
    __shared__ float s_ln[64];

    const int tid = threadIdx.x;
    const int b   = blockIdx.x;

    // ---------- stage x row + conv weights ----------
    {
        const float4* x4 = reinterpret_cast<const float4*>(x + (size_t)b * SEQIN);
        float4* q4 = reinterpret_cast<float4*>(s_att);
        for (int i = tid; i < SEQIN / 4; i += NT) q4[i] = x4[i];
    }
    for (int i = tid; i < DD * KW; i += NT) s_Wqkv[i] = conv_w[i];
    if (tid < DD) s_bqkv[tid] = conv_b[tid];
    __syncthreads();

    // ---------- conv patch embedding ----------
    for (int idx = tid; idx < NP * DD; idx += NT) {
        int p = idx >> 4, f = idx & 15;
        float acc = s_bqkv[f];
        const float* xp = &s_att[p * KW];
        const float* wf = &s_Wqkv[f * KW];
        #pragma unroll
        for (int k = 0; k < KW; k++) acc = fmaf(xp[k], wf[k], acc);
        s_h[(p + 1) * HSTR + f] = acc;
    }
    if (tid < DD) s_h[tid] = cls_emb[tid];
    __syncthreads();

    // zero-pad slot SS (t=101) of K/V arrays once: k=0 -> score 0 -> e=1; v=0
    // (compensated by den -= 1 after the loop). Never overwritten later.
    if (tid < NHEAD) {
        s_att[KX_OFF + tid * TSTR + SS] = 0.f;
        s_att[KY_OFF + tid * TSTR + SS] = 0.f;
        s_att[VX_OFF + tid * TSTR + SS] = 0.f;
        s_att[VY_OFF + tid * TSTR + SS] = 0.f;
    }

    const float QSC = 1.44269504088896f * 0.707106781186547f; // log2e / sqrt(2)

    // ---------- transformer layers ----------
    for (int l = 0; l < LAYERS; l++) {
        for (int i = tid; i < 768; i += NT) s_Wqkv[i] = Wqkv[l * 768 + i];
        for (int i = tid; i < 256; i += NT) {
            s_Wo[i] = Wo[l * 256 + i];
            s_W1[i] = W1[l * 256 + i];
            s_W2[i] = W2[l * 256 + i];
        }
        if (tid < 48) s_bqkv[tid] = bqkv[l * 48 + tid];
        if (tid < 16) {
            s_bo[tid]      = bo[l * 16 + tid];
            s_b1[tid]      = b1[l * 16 + tid];
            s_b2[tid]      = b2[l * 16 + tid];
            s_ln[tid]      = ln1_g[l * 16 + tid];
            s_ln[16 + tid] = ln1_b[l * 16 + tid];
            s_ln[32 + tid] = ln2_g[l * 16 + tid];
            s_ln[48 + tid] = ln2_b[l * 16 + tid];
        }
        __syncthreads();

        // ---- QKV projection: h row in packed regs; ALL outputs stored
        //      transposed (stride-1 across lanes -> conflict-free STS) ----
        if (tid < SS) {
            const float4* h4 = reinterpret_cast<const float4*>(&s_h[tid * HSTR]);
            float4 hr[4] = {h4[0], h4[1], h4[2], h4[3]};
            const float* hs = reinterpret_cast<const float*>(hr);
            u64 h2[8];
            #pragma unroll
            for (int j = 0; j < 8; j++) h2[j] = pk2(hs[2*j], hs[2*j+1]);
            const u64* w2 = reinterpret_cast<const u64*>(s_Wqkv);

            #pragma unroll
            for (int hh = 0; hh < NHEAD; hh++) {
                s_att[QX_OFF + hh * TSTR + tid] = dot16p(h2, w2 + (2*hh)          * 8, s_bqkv[2*hh]);
                s_att[QY_OFF + hh * TSTR + tid] = dot16p(h2, w2 + (2*hh + 1)      * 8, s_bqkv[2*hh + 1]);
                s_att[KX_OFF + hh * TSTR + tid] = dot16p(h2, w2 + (16 + 2*hh)     * 8, s_bqkv[16 + 2*hh]);
                s_att[KY_OFF + hh * TSTR + tid] = dot16p(h2, w2 + (16 + 2*hh + 1) * 8, s_bqkv[16 + 2*hh + 1]);
                s_att[VX_OFF + hh * TSTR + tid] = dot16p(h2, w2 + (32 + 2*hh)     * 8, s_bqkv[32 + 2*hh]);
                s_att[VY_OFF + hh * TSTR + tid] = dot16p(h2, w2 + (32 + 2*hh + 1) * 8, s_bqkv[32 + 2*hh + 1]);
            }
        }
        __syncthreads();

        // ---- attention: packed over t-pairs, single-pass softmax,
        //      every 4th pair's exps on the FMA pipe (hoisted constants) ----
        {
            const bool active = (tid < NHEAD * NBLK);
            int hh = 0, s0 = 0;
            u64 qx2[QB], qy2[QB];
            if (active) {
                hh = tid / NBLK;
                s0 = (tid - hh * NBLK) * QB;
                #pragma unroll
                for (int i = 0; i < QB; i++) {
                    int s = s0 + i;
                    float qx = s_att[QX_OFF + hh * TSTR + s] * QSC;
                    float qy = s_att[QY_OFF + hh * TSTR + s] * QSC;
                    qx2[i] = pk2(qx, qx);
                    qy2[i] = pk2(qy, qy);
                }
            }
            // all q loads complete before ctx overwrites the QX/QY region
            __syncthreads();
            if (active) {
                // hoist poly constants into loop-invariant registers
                const u64 C12  = pk2( 12582912.f,  12582912.f);
                const u64 mC12 = pk2(-12582912.f, -12582912.f);
                const u64 mONE = pk2(-1.f, -1.f);
                const u64 cc4  = pk2(9.6181291e-3f, 9.6181291e-3f);
                const u64 cc3  = pk2(5.5504109e-2f, 5.5504109e-2f);
                const u64 cc2  = pk2(2.4022651e-1f, 2.4022651e-1f);
                const u64 cc1  = pk2(6.9314718e-1f, 6.9314718e-1f);
                const u64 ONE  = pk2(1.f, 1.f);

                u64 den2[QB], cx2[QB], cy2[QB];
                #pragma unroll
                for (int i = 0; i < QB; i++) { den2[i] = 0ull; cx2[i] = 0ull; cy2[i] = 0ull; }

                const u64* kxp = reinterpret_cast<const u64*>(&s_att[KX_OFF + hh * TSTR]);
                const u64* kyp = reinterpret_cast<const u64*>(&s_att[KY_OFF + hh * TSTR]);
                const u64* vxp = reinterpret_cast<const u64*>(&s_att[VX_OFF + hh * TSTR]);
                const u64* vyp = reinterpret_cast<const u64*>(&s_att[VY_OFF + hh * TSTR]);

                int tp = 0;
                #pragma unroll 1
                for (int g = 0; g < 12; g++, tp += 4) {   // pairs 0..47
                    #pragma unroll
                    for (int m = 0; m < 4; m++) {
                        u64 kx2 = kxp[tp + m], ky2 = kyp[tp + m];
                        u64 vx2 = vxp[tp + m], vy2 = vyp[tp + m];
                        #pragma unroll
                        for (int i = 0; i < QB; i++) {
                            u64 sc2 = fma2_(qy2[i], ky2, mul2_(qx2[i], kx2));
                            u64 e2  = (m == 3)
                                    ? exp2poly(sc2, C12, mC12, mONE, cc4, cc3, cc2, cc1, ONE)
                                    : exp2m(sc2);
                            den2[i] = add2_(den2[i], e2);
                            cx2[i]  = fma2_(e2, vx2, cx2[i]);
                            cy2[i]  = fma2_(e2, vy2, cy2[i]);
                        }
                    }
                }
                #pragma unroll
                for (int m = 0; m < 3; m++) {             // pairs 48..50 (50 holds pad slot)
                    u64 kx2 = kxp[48 + m], ky2 = kyp[48 + m];
                    u64 vx2 = vxp[48 + m], vy2 = vyp[48 + m];
                    #pragma unroll
                    for (int i = 0; i < QB; i++) {
                        u64 sc2 = fma2_(qy2[i], ky2, mul2_(qx2[i], kx2));
                        u64 e2  = exp2m(sc2);
                        den2[i] = add2_(den2[i], e2);
                        cx2[i]  = fma2_(e2, vx2, cx2[i]);
                        cy2[i]  = fma2_(e2, vy2, cy2[i]);
                    }
                }

                u64* ctx_u64 = reinterpret_cast<u64*>(s_att);   // QX+QY region
                #pragma unroll
                for (int i = 0; i < QB; i++) {
                    int s = s0 + i;
                    if (s < SS) {
                        float d0, d1, a0, a1;
                        upk2(den2[i], d0, d1); float den = d0 + d1 - 1.f; // pad slot
                        upk2(cx2[i],  a0, a1); float cx  = a0 + a1;
                        upk2(cy2[i],  a0, a1); float cy  = a0 + a1;
                        float inv = rcpf_fast(den);
                        ctx_u64[hh * TSTR + s] = pk2(cx * inv, cy * inv);
                    }
                }
            }
        }
        __syncthreads();

        // ---- Wo + residual + LN1 + FF1 + FF2 + residual + LN2, per row, packed ----
        if (tid < SS) {
            const u64* ctx_u64 = reinterpret_cast<const u64*>(s_att);
            u64 c2[8];
            #pragma unroll
            for (int j = 0; j < 8; j++) c2[j] = ctx_u64[j * TSTR + tid];

            const float4* h4 = reinterpret_cast<const float4*>(&s_h[tid * HSTR]);
            float4 hr4[4] = {h4[0], h4[1], h4[2], h4[3]};
            const float* hs = reinterpret_cast<const float*>(hr4);

            const u64* wo2 = reinterpret_cast<const u64*>(s_Wo);
            float vv[16];
            float mu = 0.f;
            #pragma unroll
            for (int o = 0; o < 16; o++) {
                vv[o] = dot16p(c2, wo2 + o * 8, s_bo[o]) + hs[o];
                mu += vv[o];
            }
            mu *= 0.0625f;
            float var = 0.f;
            #pragma unroll
            for (int d = 0; d < 16; d++) { float t = vv[d] - mu; var = fmaf(t, t, var); }
            float r = rsqrtf(fmaf(var, 0.0625f, 1e-5f));

            float ln1s[16];
            #pragma unroll
            for (int d = 0; d < 16; d++)
                ln1s[d] = (vv[d] - mu) * r * s_ln[d] + s_ln[16 + d];
            u64 l2[8];
            #pragma unroll
            for (int j = 0; j < 8; j++) l2[j] = pk2(ln1s[2*j], ln1s[2*j+1]);

            const u64* w12 = reinterpret_cast<const u64*>(s_W1);
            float frs[16];
            #pragma unroll
            for (int f = 0; f < 16; f++)
                frs[f] = fmaxf(dot16p(l2, w12 + f * 8, s_b1[f]), 0.f);
            u64 f2[8];
            #pragma unroll
            for (int j = 0; j < 8; j++) f2[j] = pk2(frs[2*j], frs[2*j+1]);

            const u64* w22 = reinterpret_cast<const u64*>(s_W2);
            mu = 0.f;
            #pragma unroll
            for (int d = 0; d < 16; d++) {
                vv[d] = dot16p(f2, w22 + d * 8, s_b2[d]) + ln1s[d];
                mu += vv[d];
            }
            mu *= 0.0625f;
            var = 0.f;
            #pragma unroll
            for (int d = 0; d < 16; d++) { float t = vv[d] - mu; var = fmaf(t, t, var); }
            r = rsqrtf(fmaf(var, 0.0625f, 1e-5f));

            float4 ov[4];
            float* os = reinterpret_cast<float*>(ov);
            #pragma unroll
            for (int d = 0; d < 16; d++)
                os[d] = (vv[d] - mu) * r * s_ln[32 + d] + s_ln[48 + d];
            float4* oh = reinterpret_cast<float4*>(&s_h[tid * HSTR]);
            oh[0] = ov[0]; oh[1] = ov[1]; oh[2] = ov[2]; oh[3] = ov[3];
        }
        __syncthreads();
    }

    // ---------- final LN (cls row) ----------
    if (tid == 0) {
        float mu = 0.f;
        #pragma unroll
        for (int d = 0; d < 16; d++) mu += s_h[d];
        mu *= 0.0625f;
        float var = 0.f;
        #pragma unroll
        for (int d = 0; d < 16; d++) { float t = s_h[d] - mu; var = fmaf(t, t, var); }
        float r = rsqrtf(fmaf(var, 0.0625f, 1e-5f));
        #pragma unroll
        for (int d = 0; d < 16; d++)
            s_att[d] = (s_h[d] - mu) * r * lnf_g[d] + lnf_b[d];
    }
    __syncthreads();

    // ---------- end projection (fused with head weight) ----------
    if (tid < 100) {
        float acc = end_b[tid];
        #pragma unroll
        for (int d = 0; d < 16; d++) acc = fmaf(s_att[d], end_w[tid * 16 + d], acc);
        s_att[64 + tid] = acc * head_w[tid];
    }
    __syncthreads();

    // ---------- head sum + sigmoid ----------
    if (tid == 0) {
        float acc = head_b[0];
        #pragma unroll 4
        for (int j = 0; j < 100; j++) acc += s_att[64 + j];
        out[b] = 1.f / (1.f + ex2f_fast(-acc * 1.44269504088896f));
    }
}

extern "C" void kernel_launch(void* const* d_in, const int* in_sizes, int n_in,
                              void* d_out, int out_size) {
    const float* x       = (const float*)d_in[0];
    const float* conv_w  = (const float*)d_in[1];
    const float* conv_b  = (const float*)d_in[2];
    const float* cls_emb = (const float*)d_in[3];
    const float* Wqkv    = (const float*)d_in[4];
    const float* bqkv    = (const float*)d_in[5];
    const float* Wo      = (const float*)d_in[6];
    const float* bo      = (const float*)d_in[7];
    const float* W1      = (const float*)d_in[8];
    const float* b1      = (const float*)d_in[9];
    const float* W2      = (const float*)d_in[10];
    const float* b2      = (const float*)d_in[11];
    const float* ln1_g   = (const float*)d_in[12];
    const float* ln1_b   = (const float*)d_in[13];
    const float* ln2_g   = (const float*)d_in[14];
    const float* ln2_b   = (const float*)d_in[15];
    const float* lnf_g   = (const float*)d_in[16];
    const float* lnf_b   = (const float*)d_in[17];
    const float* end_w   = (const float*)d_in[18];
    const float* end_b   = (const float*)d_in[19];
    const float* head_w  = (const float*)d_in[20];
    const float* head_b  = (const float*)d_in[21];

    int B = in_sizes[0] / SEQIN;

    TorrinE0_fused_kernel<<<B, NT>>>(
        x, conv_w, conv_b, cls_emb, Wqkv, bqkv, Wo, bo, W1, b1, W2, b2,
        ln1_g, ln1_b, ln2_g, ln2_b, lnf_g, lnf_b, end_w, end_b, head_w, head_b,
        (float*)d_out);
}

// round 16
// speedup vs baseline: 1.1484x; 1.1484x over previous
#include <cuda_runtime.h>
#include <cuda_bf16.h>
#include <cuda_fp16.h>

#define DD     16
#define NHEAD  8
#define LAYERS 8
#define FFD    16
#define KW     35
#define SEQIN  3500
#define NP     100
#define SS     101
#define HSTR   20      // s_h row stride (16B-aligned rows)
#define NT     128
#define QB     7       // query rows per attention task
#define NBLK   15      // ceil(SS/QB) -> 8*15 = 120 tasks
#define TSTR   104     // per-head slot stride in s_att regions (even)

// s_att float regions (each 8 heads * TSTR floats = 832): QX, QY, KX, KY
#define QX_OFF 0
#define QY_OFF 832
#define KX_OFF 1664
#define KY_OFF 2496
#define ATT_SZ 3500    // >= 3328 regions; also holds x (3500) during conv

typedef unsigned long long u64;
typedef unsigned int u32;

__device__ __forceinline__ float ex2f_fast(float x) {
    float y;
    asm("ex2.approx.ftz.f32 %0, %1;" : "=f"(y) : "f"(x));
    return y;
}
__device__ __forceinline__ float rcpf_fast(float x) {
    float y;
    asm("rcp.approx.ftz.f32 %0, %1;" : "=f"(y) : "f"(x));
    return y;
}
__device__ __forceinline__ u64 pk2(float lo, float hi) {
    u64 r; asm("mov.b64 %0, {%1, %2};" : "=l"(r) : "f"(lo), "f"(hi)); return r;
}
__device__ __forceinline__ void upk2(u64 v, float& lo, float& hi) {
    asm("mov.b64 {%0, %1}, %2;" : "=f"(lo), "=f"(hi) : "l"(v));
}
__device__ __forceinline__ u64 fma2_(u64 a, u64 b, u64 c) {
    u64 r; asm("fma.rn.f32x2 %0, %1, %2, %3;" : "=l"(r) : "l"(a), "l"(b), "l"(c)); return r;
}
__device__ __forceinline__ u64 mul2_(u64 a, u64 b) {
    u64 r; asm("mul.rn.f32x2 %0, %1, %2;" : "=l"(r) : "l"(a), "l"(b)); return r;
}

// both exps of a packed f32x2 score pair -> f16x2 result (lo = lo-score's exp)
__device__ __forceinline__ u32 exp2h16(u64 sc2) {
    float a, b; upk2(sc2, a, b);
    u32 p, e;
    asm("cvt.rn.f16x2.f32 %0, %1, %2;" : "=r"(p) : "f"(b), "f"(a)); // hi=b, lo=a
    asm("ex2.approx.f16x2 %0, %1;" : "=r"(e) : "r"(p));
    return e;
}
__device__ __forceinline__ u32 hadd2_(u32 a, u32 b) {
    u32 r; asm("add.rn.f16x2 %0, %1, %2;" : "=r"(r) : "r"(a), "r"(b)); return r;
}
__device__ __forceinline__ u32 hfma2_(u32 a, u32 b, u32 c) {
    u32 r; asm("fma.rn.f16x2 %0, %1, %2, %3;" : "=r"(r) : "r"(a), "r"(b), "r"(c)); return r;
}
// sum both f16 halves into f32
__device__ __forceinline__ float h2sum(u32 h) {
    float lo, hi;
    asm("{\n\t.reg .f16 l, hh;\n\t"
        "mov.b32 {l, hh}, %2;\n\t"
        "cvt.f32.f16 %0, l;\n\t"
        "cvt.f32.f16 %1, hh;\n\t}"
        : "=f"(lo), "=f"(hi) : "r"(h));
    return lo + hi;
}

// packed 16-dot: a2 = 8 packed activation pairs (regs), w2 = smem weight row as u64*
__device__ __forceinline__ float dot16p(const u64* a2, const u64* __restrict__ w2, float bias) {
    u64 acc = pk2(bias, 0.f);
    #pragma unroll
    for (int j = 0; j < 8; j++) acc = fma2_(a2[j], w2[j], acc);
    float lo, hi; upk2(acc, lo, hi);
    return lo + hi;
}

__global__ __launch_bounds__(NT, 5) void TorrinE0_fused_kernel(
    const float* __restrict__ x,      const float* __restrict__ conv_w, const float* __restrict__ conv_b,
    const float* __restrict__ cls_emb,const float* __restrict__ Wqkv,   const float* __restrict__ bqkv,
    const float* __restrict__ Wo,     const float* __restrict__ bo,
    const float* __restrict__ W1,     const float* __restrict__ b1,
    const float* __restrict__ W2,     const float* __restrict__ b2,
    const float* __restrict__ ln1_g,  const float* __restrict__ ln1_b,
    const float* __restrict__ ln2_g,  const float* __restrict__ ln2_b,
    const float* __restrict__ lnf_g,  const float* __restrict__ lnf_b,
    const float* __restrict__ end_w,  const float* __restrict__ end_b,
    const float* __restrict__ head_w, const float* __restrict__ head_b,
    float* __restrict__ out)
{
    __shared__ __align__(16) float  s_h   [SS * HSTR];
    __shared__ __align__(16) float  s_att [ATT_SZ];
    __shared__ __align__(16) __half s_vxh [NHEAD * TSTR];   // V.x as f16, per (head, t)
    __shared__ __align__(16) __half s_vyh [NHEAD * TSTR];
    __shared__ __align__(16) float  s_Wqkv[768];             // holds conv_w (560) during conv
    __shared__ __align__(16) float  s_bqkv[48];
    __shared__ __align__(16) float  s_Wo[256], s_W1[256], s_W2[256];
    __shared__ float s_bo[16],  s_b1[16], s_b2[16];
    __shared__ float s_ln[64];

    const int tid = threadIdx.x;
    const int b   = blockIdx.x;

    // ---------- stage x row + conv weights ----------
    {
        const float4* x4 = reinterpret_cast<const float4*>(x + (size_t)b * SEQIN);
        float4* q4 = reinterpret_cast<float4*>(s_att);
        for (int i = tid; i < SEQIN / 4; i += NT) q4[i] = x4[i];
    }
    for (int i = tid; i < DD * KW; i += NT) s_Wqkv[i] = conv_w[i];
    if (tid < DD) s_bqkv[tid] = conv_b[tid];
    __syncthreads();

    // ---------- conv patch embedding ----------
    for (int idx = tid; idx < NP * DD; idx += NT) {
        int p = idx >> 4, f = idx & 15;
        float acc = s_bqkv[f];
        const float* xp = &s_att[p * KW];
        const float* wf = &s_Wqkv[f * KW];
        #pragma unroll
        for (int k = 0; k < KW; k++) acc = fmaf(xp[k], wf[k], acc);
        s_h[(p + 1) * HSTR + f] = acc;
    }
    if (tid < DD) s_h[tid] = cls_emb[tid];
    __syncthreads();

    // zero-pad slot SS (t=101): k=0 -> score 0 -> e=1 (den-1 compensates); v=0.
    if (tid < NHEAD) {
        s_att[KX_OFF + tid * TSTR + SS] = 0.f;
        s_att[KY_OFF + tid * TSTR + SS] = 0.f;
        s_vxh[tid * TSTR + SS] = __float2half(0.f);
        s_vyh[tid * TSTR + SS] = __float2half(0.f);
    }

    const float QSC = 1.44269504088896f * 0.707106781186547f; // log2e / sqrt(2)

    // ---------- transformer layers ----------
    for (int l = 0; l < LAYERS; l++) {
        for (int i = tid; i < 768; i += NT) s_Wqkv[i] = Wqkv[l * 768 + i];
        for (int i = tid; i < 256; i += NT) {
            s_Wo[i] = Wo[l * 256 + i];
            s_W1[i] = W1[l * 256 + i];
            s_W2[i] = W2[l * 256 + i];
        }
        if (tid < 48) s_bqkv[tid] = bqkv[l * 48 + tid];
        if (tid < 16) {
            s_bo[tid]      = bo[l * 16 + tid];
            s_b1[tid]      = b1[l * 16 + tid];
            s_b2[tid]      = b2[l * 16 + tid];
            s_ln[tid]      = ln1_g[l * 16 + tid];
            s_ln[16 + tid] = ln1_b[l * 16 + tid];
            s_ln[32 + tid] = ln2_g[l * 16 + tid];
            s_ln[48 + tid] = ln2_b[l * 16 + tid];
        }
        __syncthreads();

        // ---- QKV projection: h row in packed regs; outputs transposed.
        //      V is stored as f16 (consumed by f16x2 attention math). ----
        if (tid < SS) {
            const float4* h4 = reinterpret_cast<const float4*>(&s_h[tid * HSTR]);
            float4 hr[4] = {h4[0], h4[1], h4[2], h4[3]};
            const float* hs = reinterpret_cast<const float*>(hr);
            u64 h2[8];
            #pragma unroll
            for (int j = 0; j < 8; j++) h2[j] = pk2(hs[2*j], hs[2*j+1]);
            const u64* w2 = reinterpret_cast<const u64*>(s_Wqkv);

            #pragma unroll
            for (int hh = 0; hh < NHEAD; hh++) {
                s_att[QX_OFF + hh * TSTR + tid] = dot16p(h2, w2 + (2*hh)          * 8, s_bqkv[2*hh]);
                s_att[QY_OFF + hh * TSTR + tid] = dot16p(h2, w2 + (2*hh + 1)      * 8, s_bqkv[2*hh + 1]);
                s_att[KX_OFF + hh * TSTR + tid] = dot16p(h2, w2 + (16 + 2*hh)     * 8, s_bqkv[16 + 2*hh]);
                s_att[KY_OFF + hh * TSTR + tid] = dot16p(h2, w2 + (16 + 2*hh + 1) * 8, s_bqkv[16 + 2*hh + 1]);
                s_vxh[hh * TSTR + tid] = __float2half(dot16p(h2, w2 + (32 + 2*hh)     * 8, s_bqkv[32 + 2*hh]));
                s_vyh[hh * TSTR + tid] = __float2half(dot16p(h2, w2 + (32 + 2*hh + 1) * 8, s_bqkv[32 + 2*hh + 1]));
            }
        }
        __syncthreads();

        // ---- attention: packed t-pairs, single-pass softmax,
        //      f16x2 exp + f16x2 accumulation, f32 flush every 16 pairs ----
        {
            const bool active = (tid < NHEAD * NBLK);
            int hh = 0, s0 = 0;
            u64 qx2[QB], qy2[QB];
            if (active) {
                hh = tid / NBLK;
                s0 = (tid - hh * NBLK) * QB;
                #pragma unroll
                for (int i = 0; i < QB; i++) {
                    int s = s0 + i;
                    float qx = s_att[QX_OFF + hh * TSTR + s] * QSC;
                    float qy = s_att[QY_OFF + hh * TSTR + s] * QSC;
                    qx2[i] = pk2(qx, qx);
                    qy2[i] = pk2(qy, qy);
                }
            }
            // all q loads complete before ctx overwrites the QX/QY region
            __syncthreads();
            if (active) {
                float denf[QB], cxf[QB], cyf[QB];
                u32 dh[QB], cxh[QB], cyh[QB];
                #pragma unroll
                for (int i = 0; i < QB; i++) {
                    denf[i] = 0.f; cxf[i] = 0.f; cyf[i] = 0.f;
                    dh[i] = 0u; cxh[i] = 0u; cyh[i] = 0u;
                }

                const u64* kxp = reinterpret_cast<const u64*>(&s_att[KX_OFF + hh * TSTR]);
                const u64* kyp = reinterpret_cast<const u64*>(&s_att[KY_OFF + hh * TSTR]);
                const u32* vxp = reinterpret_cast<const u32*>(s_vxh + hh * TSTR);
                const u32* vyp = reinterpret_cast<const u32*>(s_vyh + hh * TSTR);

                #pragma unroll 1
                for (int g = 0; g < 3; g++) {            // 3 groups of 16 pairs (0..47)
                    #pragma unroll 4
                    for (int mm = 0; mm < 16; mm++) {
                        int tp = g * 16 + mm;
                        u64 kx2 = kxp[tp], ky2 = kyp[tp];
                        u32 vxh = vxp[tp], vyh = vyp[tp];
                        #pragma unroll
                        for (int i = 0; i < QB; i++) {
                            u64 sc2 = fma2_(qy2[i], ky2, mul2_(qx2[i], kx2));
                            u32 eh  = exp2h16(sc2);
                            dh[i]  = hadd2_(dh[i], eh);
                            cxh[i] = hfma2_(eh, vxh, cxh[i]);
                            cyh[i] = hfma2_(eh, vyh, cyh[i]);
                        }
                    }
                    // flush f16 partials into f32 totals (bounds f16 error)
                    #pragma unroll
                    for (int i = 0; i < QB; i++) {
                        denf[i] += h2sum(dh[i]);  dh[i]  = 0u;
                        cxf[i]  += h2sum(cxh[i]); cxh[i] = 0u;
                        cyf[i]  += h2sum(cyh[i]); cyh[i] = 0u;
                    }
                }
                #pragma unroll
                for (int m = 0; m < 3; m++) {            // pairs 48..50 (50 holds pad slot)
                    u64 kx2 = kxp[48 + m], ky2 = kyp[48 + m];
                    u32 vxh = vxp[48 + m], vyh = vyp[48 + m];
                    #pragma unroll
                    for (int i = 0; i < QB; i++) {
                        u64 sc2 = fma2_(qy2[i], ky2, mul2_(qx2[i], kx2));
                        u32 eh  = exp2h16(sc2);
                        dh[i]  = hadd2_(dh[i], eh);
                        cxh[i] = hfma2_(eh, vxh, cxh[i]);
                        cyh[i] = hfma2_(eh, vyh, cyh[i]);
                    }
                }

                u64* ctx_u64 = reinterpret_cast<u64*>(s_att);   // QX+QY region
                #pragma unroll
                for (int i = 0; i < QB; i++) {
                    int s = s0 + i;
                    if (s < SS) {
                        float den = denf[i] + h2sum(dh[i])  - 1.f;  // pad slot e=1
                        float cx  = cxf[i]  + h2sum(cxh[i]);
                        float cy  = cyf[i]  + h2sum(cyh[i]);
                        float inv = rcpf_fast(den);
                        ctx_u64[hh * TSTR + s] = pk2(cx * inv, cy * inv);
                    }
                }
            }
        }
        __syncthreads();

        // ---- Wo + residual + LN1 + FF1 + FF2 + residual + LN2, per row, packed ----
        if (tid < SS) {
            const u64* ctx_u64 = reinterpret_cast<const u64*>(s_att);
            u64 c2[8];
            #pragma unroll
            for (int j = 0; j < 8; j++) c2[j] = ctx_u64[j * TSTR + tid];

            const float4* h4 = reinterpret_cast<const float4*>(&s_h[tid * HSTR]);
            float4 hr4[4] = {h4[0], h4[1], h4[2], h4[3]};
            const float* hs = reinterpret_cast<const float*>(hr4);

            const u64* wo2 = reinterpret_cast<const u64*>(s_Wo);
            float vv[16];
            float mu = 0.f;
            #pragma unroll
            for (int o = 0; o < 16; o++) {
                vv[o] = dot16p(c2, wo2 + o * 8, s_bo[o]) + hs[o];
                mu += vv[o];
            }
            mu *= 0.0625f;
            float var = 0.f;
            #pragma unroll
            for (int d = 0; d < 16; d++) { float t = vv[d] - mu; var = fmaf(t, t, var); }
            float r = rsqrtf(fmaf(var, 0.0625f, 1e-5f));

            float ln1s[16];
            #pragma unroll
            for (int d = 0; d < 16; d++)
                ln1s[d] = (vv[d] - mu) * r * s_ln[d] + s_ln[16 + d];
            u64 l2[8];
            #pragma unroll
            for (int j = 0; j < 8; j++) l2[j] = pk2(ln1s[2*j], ln1s[2*j+1]);

            const u64* w12 = reinterpret_cast<const u64*>(s_W1);
            float frs[16];
            #pragma unroll
            for (int f = 0; f < 16; f++)
                frs[f] = fmaxf(dot16p(l2, w12 + f * 8, s_b1[f]), 0.f);
            u64 f2[8];
            #pragma unroll
            for (int j = 0; j < 8; j++) f2[j] = pk2(frs[2*j], frs[2*j+1]);

            const u64* w22 = reinterpret_cast<const u64*>(s_W2);
            mu = 0.f;
            #pragma unroll
            for (int d = 0; d < 16; d++) {
                vv[d] = dot16p(f2, w22 + d * 8, s_b2[d]) + ln1s[d];
                mu += vv[d];
            }
            mu *= 0.0625f;
            var = 0.f;
            #pragma unroll
            for (int d = 0; d < 16; d++) { float t = vv[d] - mu; var = fmaf(t, t, var); }
            r = rsqrtf(fmaf(var, 0.0625f, 1e-5f));

            float4 ov[4];
            float* os = reinterpret_cast<float*>(ov);
            #pragma unroll
            for (int d = 0; d < 16; d++)
                os[d] = (vv[d] - mu) * r * s_ln[32 + d] + s_ln[48 + d];
            float4* oh = reinterpret_cast<float4*>(&s_h[tid * HSTR]);
            oh[0] = ov[0]; oh[1] = ov[1]; oh[2] = ov[2]; oh[3] = ov[3];
        }
        __syncthreads();
    }

    // ---------- final LN (cls row) ----------
    if (tid == 0) {
        float mu = 0.f;
        #pragma unroll
        for (int d = 0; d < 16; d++) mu += s_h[d];
        mu *= 0.0625f;
        float var = 0.f;
        #pragma unroll
        for (int d = 0; d < 16; d++) { float t = s_h[d] - mu; var = fmaf(t, t, var); }
        float r = rsqrtf(fmaf(var, 0.0625f, 1e-5f));
        #pragma unroll
        for (int d = 0; d < 16; d++)
            s_att[d] = (s_h[d] - mu) * r * lnf_g[d] + lnf_b[d];
    }
    __syncthreads();

    // ---------- end projection (fused with head weight) ----------
    if (tid < 100) {
        float acc = end_b[tid];
        #pragma unroll
        for (int d = 0; d < 16; d++) acc = fmaf(s_att[d], end_w[tid * 16 + d], acc);
        s_att[64 + tid] = acc * head_w[tid];
    }
    __syncthreads();

    // ---------- head sum + sigmoid ----------
    if (tid == 0) {
        float acc = head_b[0];
        #pragma unroll 4
        for (int j = 0; j < 100; j++) acc += s_att[64 + j];
        out[b] = 1.f / (1.f + ex2f_fast(-acc * 1.44269504088896f));
    }
}

extern "C" void kernel_launch(void* const* d_in, const int* in_sizes, int n_in,
                              void* d_out, int out_size) {
    const float* x       = (const float*)d_in[0];
    const float* conv_w  = (const float*)d_in[1];
    const float* conv_b  = (const float*)d_in[2];
    const float* cls_emb = (const float*)d_in[3];
    const float* Wqkv    = (const float*)d_in[4];
    const float* bqkv    = (const float*)d_in[5];
    const float* Wo      = (const float*)d_in[6];
    const float* bo      = (const float*)d_in[7];
    const float* W1      = (const float*)d_in[8];
    const float* b1      = (const float*)d_in[9];
    const float* W2      = (const float*)d_in[10];
    const float* b2      = (const float*)d_in[11];
    const float* ln1_g   = (const float*)d_in[12];
    const float* ln1_b   = (const float*)d_in[13];
    const float* ln2_g   = (const float*)d_in[14];
    const float* ln2_b   = (const float*)d_in[15];
    const float* lnf_g   = (const float*)d_in[16];
    const float* lnf_b   = (const float*)d_in[17];
    const float* end_w   = (const float*)d_in[18];
    const float* end_b   = (const float*)d_in[19];
    const float* head_w  = (const float*)d_in[20];
    const float* head_b  = (const float*)d_in[21];

    int B = in_sizes[0] / SEQIN;

    TorrinE0_fused_kernel<<<B, NT>>>(
        x, conv_w, conv_b, cls_emb, Wqkv, bqkv, Wo, bo, W1, b1, W2, b2,
        ln1_g, ln1_b, ln2_g, ln2_b, lnf_g, lnf_b, end_w, end_b, head_w, head_b,
        (float*)d_out);
}

// round 17
// speedup vs baseline: 1.2112x; 1.0546x over previous
#include <cuda_runtime.h>
#include <cuda_bf16.h>
#include <cuda_fp16.h>

#define DD     16
#define NHEAD  8
#define LAYERS 8
#define FFD    16
#define KW     35
#define SEQIN  3500
#define NP     100
#define SS     101
#define HSTR   20      // s_h row stride (16B-aligned rows)
#define NT     128
#define QB     7       // query rows per attention task
#define NBLK   15      // ceil(SS/QB) -> 8*15 = 120 tasks
#define TSTR   104     // per-head slot stride (even -> u32 f16-pair loads aligned)

// s_att float regions: QX, QY (f32); also holds x (3500) during conv
#define QX_OFF 0
#define QY_OFF 832
#define ATT_SZ 3500

typedef unsigned long long u64;
typedef unsigned int u32;

__device__ __forceinline__ float ex2f_fast(float x) {
    float y;
    asm("ex2.approx.ftz.f32 %0, %1;" : "=f"(y) : "f"(x));
    return y;
}
__device__ __forceinline__ float rcpf_fast(float x) {
    float y;
    asm("rcp.approx.ftz.f32 %0, %1;" : "=f"(y) : "f"(x));
    return y;
}
__device__ __forceinline__ u64 pk2(float lo, float hi) {
    u64 r; asm("mov.b64 %0, {%1, %2};" : "=l"(r) : "f"(lo), "f"(hi)); return r;
}
__device__ __forceinline__ void upk2(u64 v, float& lo, float& hi) {
    asm("mov.b64 {%0, %1}, %2;" : "=f"(lo), "=f"(hi) : "l"(v));
}
__device__ __forceinline__ u64 fma2_(u64 a, u64 b, u64 c) {
    u64 r; asm("fma.rn.f32x2 %0, %1, %2, %3;" : "=l"(r) : "l"(a), "l"(b), "l"(c)); return r;
}

// f16x2 helpers
__device__ __forceinline__ u32 h2bcast(float v) {        // (v, v) as f16x2
    u32 r; asm("cvt.rn.f16x2.f32 %0, %1, %1;" : "=r"(r) : "f"(v)); return r;
}
__device__ __forceinline__ u32 hmul2_(u32 a, u32 b) {
    u32 r; asm("mul.rn.f16x2 %0, %1, %2;" : "=r"(r) : "r"(a), "r"(b)); return r;
}
__device__ __forceinline__ u32 hfma2_(u32 a, u32 b, u32 c) {
    u32 r; asm("fma.rn.f16x2 %0, %1, %2, %3;" : "=r"(r) : "r"(a), "r"(b), "r"(c)); return r;
}
__device__ __forceinline__ u32 hadd2_(u32 a, u32 b) {
    u32 r; asm("add.rn.f16x2 %0, %1, %2;" : "=r"(r) : "r"(a), "r"(b)); return r;
}
__device__ __forceinline__ u32 hex2_(u32 a) {
    u32 r; asm("ex2.approx.f16x2 %0, %1;" : "=r"(r) : "r"(a)); return r;
}
// sum both f16 halves into f32
__device__ __forceinline__ float h2sum(u32 h) {
    float lo, hi;
    asm("{\n\t.reg .f16 l, hh;\n\t"
        "mov.b32 {l, hh}, %2;\n\t"
        "cvt.f32.f16 %0, l;\n\t"
        "cvt.f32.f16 %1, hh;\n\t}"
        : "=f"(lo), "=f"(hi) : "r"(h));
    return lo + hi;
}

// packed 16-dot: a2 = 8 packed activation pairs (regs), w2 = smem weight row as u64*
__device__ __forceinline__ float dot16p(const u64* a2, const u64* __restrict__ w2, float bias) {
    u64 acc = pk2(bias, 0.f);
    #pragma unroll
    for (int j = 0; j < 8; j++) acc = fma2_(a2[j], w2[j], acc);
    float lo, hi; upk2(acc, lo, hi);
    return lo + hi;
}

__global__ __launch_bounds__(NT, 5) void TorrinE0_fused_kernel(
    const float* __restrict__ x,      const float* __restrict__ conv_w, const float* __restrict__ conv_b,
    const float* __restrict__ cls_emb,const float* __restrict__ Wqkv,   const float* __restrict__ bqkv,
    const float* __restrict__ Wo,     const float* __restrict__ bo,
    const float* __restrict__ W1,     const float* __restrict__ b1,
    const float* __restrict__ W2,     const float* __restrict__ b2,
    const float* __restrict__ ln1_g,  const float* __restrict__ ln1_b,
    const float* __restrict__ ln2_g,  const float* __restrict__ ln2_b,
    const float* __restrict__ lnf_g,  const float* __restrict__ lnf_b,
    const float* __restrict__ end_w,  const float* __restrict__ end_b,
    const float* __restrict__ head_w, const float* __restrict__ head_b,
    float* __restrict__ out)
{
    __shared__ __align__(16) float  s_h   [SS * HSTR];
    __shared__ __align__(16) float  s_att [ATT_SZ];
    __shared__ __align__(16) __half s_kxh [NHEAD * TSTR];   // K.x as f16, per (head, t)
    __shared__ __align__(16) __half s_kyh [NHEAD * TSTR];
    __shared__ __align__(16) __half s_vxh [NHEAD * TSTR];   // V.x as f16
    __shared__ __align__(16) __half s_vyh [NHEAD * TSTR];
    __shared__ __align__(16) float  s_Wqkv[768];             // holds conv_w (560) during conv
    __shared__ __align__(16) float  s_bqkv[48];
    __shared__ __align__(16) float  s_Wo[256], s_W1[256], s_W2[256];
    __shared__ float s_bo[16],  s_b1[16], s_b2[16];
    __shared__ float s_ln[64];

    const int tid = threadIdx.x;
    const int b   = blockIdx.x;

    // ---------- stage x row + conv weights ----------
    {
        const float4* x4 = reinterpret_cast<const float4*>(x + (size_t)b * SEQIN);
        float4* q4 = reinterpret_cast<float4*>(s_att);
        for (int i = tid; i < SEQIN / 4; i += NT) q4[i] = x4[i];
    }
    for (int i = tid; i < DD * KW; i += NT) s_Wqkv[i] = conv_w[i];
    if (tid < DD) s_bqkv[tid] = conv_b[tid];
    __syncthreads();

    // ---------- conv patch embedding ----------
    for (int idx = tid; idx < NP * DD; idx += NT) {
        int p = idx >> 4, f = idx & 15;
        float acc = s_bqkv[f];
        const float* xp = &s_att[p * KW];
        const float* wf = &s_Wqkv[f * KW];
        #pragma unroll
        for (int k = 0; k < KW; k++) acc = fmaf(xp[k], wf[k], acc);
        s_h[(p + 1) * HSTR + f] = acc;
    }
    if (tid < DD) s_h[tid] = cls_emb[tid];
    __syncthreads();

    // zero-pad slot SS (t=101): k=0 -> score 0 -> e=1 (den-1 compensates); v=0.
    if (tid < NHEAD) {
        s_kxh[tid * TSTR + SS] = __float2half(0.f);
        s_kyh[tid * TSTR + SS] = __float2half(0.f);
        s_vxh[tid * TSTR + SS] = __float2half(0.f);
        s_vyh[tid * TSTR + SS] = __float2half(0.f);
    }

    const float QSC = 1.44269504088896f * 0.707106781186547f; // log2e / sqrt(2)

    // ---------- transformer layers ----------
    for (int l = 0; l < LAYERS; l++) {
        for (int i = tid; i < 768; i += NT) s_Wqkv[i] = Wqkv[l * 768 + i];
        for (int i = tid; i < 256; i += NT) {
            s_Wo[i] = Wo[l * 256 + i];
            s_W1[i] = W1[l * 256 + i];
            s_W2[i] = W2[l * 256 + i];
        }
        if (tid < 48) s_bqkv[tid] = bqkv[l * 48 + tid];
        if (tid < 16) {
            s_bo[tid]      = bo[l * 16 + tid];
            s_b1[tid]      = b1[l * 16 + tid];
            s_b2[tid]      = b2[l * 16 + tid];
            s_ln[tid]      = ln1_g[l * 16 + tid];
            s_ln[16 + tid] = ln1_b[l * 16 + tid];
            s_ln[32 + tid] = ln2_g[l * 16 + tid];
            s_ln[48 + tid] = ln2_b[l * 16 + tid];
        }
        __syncthreads();

        // ---- QKV projection: h row in packed regs; outputs transposed.
        //      K and V stored as f16 (consumed by f16x2 attention math). ----
        if (tid < SS) {
            const float4* h4 = reinterpret_cast<const float4*>(&s_h[tid * HSTR]);
            float4 hr[4] = {h4[0], h4[1], h4[2], h4[3]};
            const float* hs = reinterpret_cast<const float*>(hr);
            u64 h2[8];
            #pragma unroll
            for (int j = 0; j < 8; j++) h2[j] = pk2(hs[2*j], hs[2*j+1]);
            const u64* w2 = reinterpret_cast<const u64*>(s_Wqkv);

            #pragma unroll
            for (int hh = 0; hh < NHEAD; hh++) {
                s_att[QX_OFF + hh * TSTR + tid] = dot16p(h2, w2 + (2*hh)          * 8, s_bqkv[2*hh]);
                s_att[QY_OFF + hh * TSTR + tid] = dot16p(h2, w2 + (2*hh + 1)      * 8, s_bqkv[2*hh + 1]);
                s_kxh[hh * TSTR + tid] = __float2half(dot16p(h2, w2 + (16 + 2*hh)     * 8, s_bqkv[16 + 2*hh]));
                s_kyh[hh * TSTR + tid] = __float2half(dot16p(h2, w2 + (16 + 2*hh + 1) * 8, s_bqkv[16 + 2*hh + 1]));
                s_vxh[hh * TSTR + tid] = __float2half(dot16p(h2, w2 + (32 + 2*hh)     * 8, s_bqkv[32 + 2*hh]));
                s_vyh[hh * TSTR + tid] = __float2half(dot16p(h2, w2 + (32 + 2*hh + 1) * 8, s_bqkv[32 + 2*hh + 1]));
            }
        }
        __syncthreads();

        // ---- attention: fully f16x2 inner math (6 slots / 2 scores),
        //      f32 flush every 16 pairs ----
        {
            const bool active = (tid < NHEAD * NBLK);
            int hh = 0, s0 = 0;
            u32 qx2[QB], qy2[QB];
            if (active) {
                hh = tid / NBLK;
                s0 = (tid - hh * NBLK) * QB;
                #pragma unroll
                for (int i = 0; i < QB; i++) {
                    int s = s0 + i;
                    qx2[i] = h2bcast(s_att[QX_OFF + hh * TSTR + s] * QSC);
                    qy2[i] = h2bcast(s_att[QY_OFF + hh * TSTR + s] * QSC);
                }
            }
            // all q loads complete before ctx overwrites the QX/QY region
            __syncthreads();
            if (active) {
                float denf[QB], cxf[QB], cyf[QB];
                u32 dh[QB], cxh[QB], cyh[QB];
                #pragma unroll
                for (int i = 0; i < QB; i++) {
                    denf[i] = 0.f; cxf[i] = 0.f; cyf[i] = 0.f;
                    dh[i] = 0u; cxh[i] = 0u; cyh[i] = 0u;
                }

                const u32* kxp = reinterpret_cast<const u32*>(s_kxh + hh * TSTR);
                const u32* kyp = reinterpret_cast<const u32*>(s_kyh + hh * TSTR);
                const u32* vxp = reinterpret_cast<const u32*>(s_vxh + hh * TSTR);
                const u32* vyp = reinterpret_cast<const u32*>(s_vyh + hh * TSTR);

                #pragma unroll 1
                for (int g = 0; g < 3; g++) {            // 3 groups of 16 pairs (0..47)
                    #pragma unroll 4
                    for (int mm = 0; mm < 16; mm++) {
                        int tp = g * 16 + mm;
                        u32 kx2 = kxp[tp], ky2 = kyp[tp];
                        u32 vxh = vxp[tp], vyh = vyp[tp];
                        #pragma unroll
                        for (int i = 0; i < QB; i++) {
                            u32 sc = hfma2_(qy2[i], ky2, hmul2_(qx2[i], kx2));
                            u32 eh = hex2_(sc);
                            dh[i]  = hadd2_(dh[i], eh);
                            cxh[i] = hfma2_(eh, vxh, cxh[i]);
                            cyh[i] = hfma2_(eh, vyh, cyh[i]);
                        }
                    }
                    // flush f16 partials into f32 totals (bounds f16 error)
                    #pragma unroll
                    for (int i = 0; i < QB; i++) {
                        denf[i] += h2sum(dh[i]);  dh[i]  = 0u;
                        cxf[i]  += h2sum(cxh[i]); cxh[i] = 0u;
                        cyf[i]  += h2sum(cyh[i]); cyh[i] = 0u;
                    }
                }
                #pragma unroll
                for (int m = 0; m < 3; m++) {            // pairs 48..50 (50 holds pad slot)
                    u32 kx2 = kxp[48 + m], ky2 = kyp[48 + m];
                    u32 vxh = vxp[48 + m], vyh = vyp[48 + m];
                    #pragma unroll
                    for (int i = 0; i < QB; i++) {
                        u32 sc = hfma2_(qy2[i], ky2, hmul2_(qx2[i], kx2));
                        u32 eh = hex2_(sc);
                        dh[i]  = hadd2_(dh[i], eh);
                        cxh[i] = hfma2_(eh, vxh, cxh[i]);
                        cyh[i] = hfma2_(eh, vyh, cyh[i]);
                    }
                }

                u64* ctx_u64 = reinterpret_cast<u64*>(s_att);   // QX+QY region
                #pragma unroll
                for (int i = 0; i < QB; i++) {
                    int s = s0 + i;
                    if (s < SS) {
                        float den = denf[i] + h2sum(dh[i])  - 1.f;  // pad slot e=1
                        float cx  = cxf[i]  + h2sum(cxh[i]);
                        float cy  = cyf[i]  + h2sum(cyh[i]);
                        float inv = rcpf_fast(den);
                        ctx_u64[hh * TSTR + s] = pk2(cx * inv, cy * inv);
                    }
                }
            }
        }
        __syncthreads();

        // ---- Wo + residual + LN1 + FF1 + FF2 + residual + LN2, per row, packed ----
        if (tid < SS) {
            const u64* ctx_u64 = reinterpret_cast<const u64*>(s_att);
            u64 c2[8];
            #pragma unroll
            for (int j = 0; j < 8; j++) c2[j] = ctx_u64[j * TSTR + tid];

            const float4* h4 = reinterpret_cast<const float4*>(&s_h[tid * HSTR]);
            float4 hr4[4] = {h4[0], h4[1], h4[2], h4[3]};
            const float* hs = reinterpret_cast<const float*>(hr4);

            const u64* wo2 = reinterpret_cast<const u64*>(s_Wo);
            float vv[16];
            float mu = 0.f;
            #pragma unroll
            for (int o = 0; o < 16; o++) {
                vv[o] = dot16p(c2, wo2 + o * 8, s_bo[o]) + hs[o];
                mu += vv[o];
            }
            mu *= 0.0625f;
            float var = 0.f;
            #pragma unroll
            for (int d = 0; d < 16; d++) { float t = vv[d] - mu; var = fmaf(t, t, var); }
            float r = rsqrtf(fmaf(var, 0.0625f, 1e-5f));

            float ln1s[16];
            #pragma unroll
            for (int d = 0; d < 16; d++)
                ln1s[d] = (vv[d] - mu) * r * s_ln[d] + s_ln[16 + d];
            u64 l2[8];
            #pragma unroll
            for (int j = 0; j < 8; j++) l2[j] = pk2(ln1s[2*j], ln1s[2*j+1]);

            const u64* w12 = reinterpret_cast<const u64*>(s_W1);
            float frs[16];
            #pragma unroll
            for (int f = 0; f < 16; f++)
                frs[f] = fmaxf(dot16p(l2, w12 + f * 8, s_b1[f]), 0.f);
            u64 f2[8];
            #pragma unroll
            for (int j = 0; j < 8; j++) f2[j] = pk2(frs[2*j], frs[2*j+1]);

            const u64* w22 = reinterpret_cast<const u64*>(s_W2);
            mu = 0.f;
            #pragma unroll
            for (int d = 0; d < 16; d++) {
                vv[d] = dot16p(f2, w22 + d * 8, s_b2[d]) + ln1s[d];
                mu += vv[d];
            }
            mu *= 0.0625f;
            var = 0.f;
            #pragma unroll
            for (int d = 0; d < 16; d++) { float t = vv[d] - mu; var = fmaf(t, t, var); }
            r = rsqrtf(fmaf(var, 0.0625f, 1e-5f));

            float4 ov[4];
            float* os = reinterpret_cast<float*>(ov);
            #pragma unroll
            for (int d = 0; d < 16; d++)
                os[d] = (vv[d] - mu) * r * s_ln[32 + d] + s_ln[48 + d];
            float4* oh = reinterpret_cast<float4*>(&s_h[tid * HSTR]);
            oh[0] = ov[0]; oh[1] = ov[1]; oh[2] = ov[2]; oh[3] = ov[3];
        }
        __syncthreads();
    }

    // ---------- final LN (cls row) ----------
    if (tid == 0) {
        float mu = 0.f;
        #pragma unroll
        for (int d = 0; d < 16; d++) mu += s_h[d];
        mu *= 0.0625f;
        float var = 0.f;
        #pragma unroll
        for (int d = 0; d < 16; d++) { float t = s_h[d] - mu; var = fmaf(t, t, var); }
        float r = rsqrtf(fmaf(var, 0.0625f, 1e-5f));
        #pragma unroll
        for (int d = 0; d < 16; d++)
            s_att[d] = (s_h[d] - mu) * r * lnf_g[d] + lnf_b[d];
    }
    __syncthreads();

    // ---------- end projection (fused with head weight) ----------
    if (tid < 100) {
        float acc = end_b[tid];
        #pragma unroll
        for (int d = 0; d < 16; d++) acc = fmaf(s_att[d], end_w[tid * 16 + d], acc);
        s_att[64 + tid] = acc * head_w[tid];
    }
    __syncthreads();

    // ---------- head sum + sigmoid ----------
    if (tid == 0) {
        float acc = head_b[0];
        #pragma unroll 4
        for (int j = 0; j < 100; j++) acc += s_att[64 + j];
        out[b] = 1.f / (1.f + ex2f_fast(-acc * 1.44269504088896f));
    }
}

extern "C" void kernel_launch(void* const* d_in, const int* in_sizes, int n_in,
                              void* d_out, int out_size) {
    const float* x       = (const float*)d_in[0];
    const float* conv_w  = (const float*)d_in[1];
    const float* conv_b  = (const float*)d_in[2];
    const float* cls_emb = (const float*)d_in[3];
    const float* Wqkv    = (const float*)d_in[4];
    const float* bqkv    = (const float*)d_in[5];
    const float* Wo      = (const float*)d_in[6];
    const float* bo      = (const float*)d_in[7];
    const float* W1      = (const float*)d_in[8];
    const float* b1      = (const float*)d_in[9];
    const float* W2      = (const float*)d_in[10];
    const float* b2      = (const float*)d_in[11];
    const float* ln1_g   = (const float*)d_in[12];
    const float* ln1_b   = (const float*)d_in[13];
    const float* ln2_g   = (const float*)d_in[14];
    const float* ln2_b   = (const float*)d_in[15];
    const float* lnf_g   = (const float*)d_in[16];
    const float* lnf_b   = (const float*)d_in[17];
    const float* end_w   = (const float*)d_in[18];
    const float* end_b   = (const float*)d_in[19];
    const float* head_w  = (const float*)d_in[20];
    const float* head_b  = (const float*)d_in[21];

    int B = in_sizes[0] / SEQIN;

    TorrinE0_fused_kernel<<<B, NT>>>(
        x, conv_w, conv_b, cls_emb, Wqkv, bqkv, Wo, bo, W1, b1, W2, b2,
        ln1_g, ln1_b, ln2_g, ln2_b, lnf_g, lnf_b, end_w, end_b, head_w, head_b,
        (float*)d_out);
}